// round 1
// baseline (speedup 1.0000x reference)
#include <cuda_runtime.h>
#include <cstdint>

#define BS 2
#define SEQ 2048
#define DMODEL 1024
#define NHEADS 16
#define DEPTH 64
#define BH (BS*NHEADS)

// Scratch (allocation-free rule: __device__ globals)
__device__ float g_Qh[BH * SEQ * DEPTH];   // [B,H,S,D]
__device__ float g_Kh[BH * SEQ * DEPTH];
__device__ float g_Vh[BH * SEQ * DEPTH];
__device__ float g_attn[BS * SEQ * DMODEL]; // [B,S,H*D] pre-Wo

// ---------------------------------------------------------------------------
// Generic projection GEMM: C[M,N] = A[M,K] @ W[K,N] + bias
// M=4096, N=K=1024. BM=BN=64, BK=16, 16x16 threads, 4x4 per thread.
// split==1: write into head-split layout [B,H,S,D]; else row-major [M,N].
// ---------------------------------------------------------------------------
__global__ void gemm_proj_kernel(const float* __restrict__ A,
                                 const float* __restrict__ W,
                                 const float* __restrict__ bias,
                                 float* __restrict__ out,
                                 int M, int N, int K, int split)
{
    const int BM = 64, BN = 64, BK = 16;
    __shared__ float As[BM][BK + 1];
    __shared__ float Bs[BK][BN + 1];

    int tx = threadIdx.x, ty = threadIdx.y;
    int tid = ty * 16 + tx;
    int m0 = blockIdx.y * BM;
    int n0 = blockIdx.x * BN;

    float acc[4][4] = {};

    for (int k0 = 0; k0 < K; k0 += BK) {
        // load A tile 64x16 (1024 elems / 256 thr = 4)
        #pragma unroll
        for (int i = 0; i < 4; i++) {
            int e = tid + i * 256;
            int r = e >> 4, c = e & 15;
            As[r][c] = A[(size_t)(m0 + r) * K + k0 + c];
        }
        // load B tile 16x64
        #pragma unroll
        for (int i = 0; i < 4; i++) {
            int e = tid + i * 256;
            int r = e >> 6, c = e & 63;
            Bs[r][c] = W[(size_t)(k0 + r) * N + n0 + c];
        }
        __syncthreads();

        #pragma unroll
        for (int k = 0; k < BK; k++) {
            float a[4], b[4];
            #pragma unroll
            for (int i = 0; i < 4; i++) a[i] = As[ty * 4 + i][k];
            #pragma unroll
            for (int j = 0; j < 4; j++) b[j] = Bs[k][tx * 4 + j];
            #pragma unroll
            for (int i = 0; i < 4; i++)
                #pragma unroll
                for (int j = 0; j < 4; j++)
                    acc[i][j] = fmaf(a[i], b[j], acc[i][j]);
        }
        __syncthreads();
    }

    #pragma unroll
    for (int i = 0; i < 4; i++) {
        int m = m0 + ty * 4 + i;
        #pragma unroll
        for (int j = 0; j < 4; j++) {
            int n = n0 + tx * 4 + j;
            float v = acc[i][j] + bias[n];
            if (split) {
                int b = m >> 11, s = m & 2047;
                int h = n >> 6, d = n & 63;
                out[(((size_t)(b * NHEADS + h) * SEQ) + s) * DEPTH + d] = v;
            } else {
                out[(size_t)m * N + n] = v;
            }
        }
    }
}

// ---------------------------------------------------------------------------
// Scores: for each (b,h): S = Qh[2048,64] @ Kh[2048,64]^T * (1/8) + mask*(-1e9)
// 64x64 tile per block, full K=64 in smem.
// ---------------------------------------------------------------------------
__global__ void scores_kernel(const float* __restrict__ Qh,
                              const float* __restrict__ Kh,
                              const float* __restrict__ mask,
                              float* __restrict__ w)
{
    __shared__ float Qs[64][65];
    __shared__ float Ks[64][65];

    int tx = threadIdx.x, ty = threadIdx.y;
    int tid = ty * 16 + tx;
    int m0 = blockIdx.y * 64;
    int n0 = blockIdx.x * 64;
    int bh = blockIdx.z;
    int b  = bh / NHEADS;

    const float* Qb = Qh + (size_t)bh * SEQ * DEPTH;
    const float* Kb = Kh + (size_t)bh * SEQ * DEPTH;

    // load 64x64 tiles (4096 elems / 256 thr = 16 each)
    #pragma unroll
    for (int i = 0; i < 16; i++) {
        int e = tid + i * 256;
        int r = e >> 6, c = e & 63;
        Qs[r][c] = Qb[(size_t)(m0 + r) * DEPTH + c];
        Ks[r][c] = Kb[(size_t)(n0 + r) * DEPTH + c];
    }
    __syncthreads();

    float acc[4][4] = {};
    #pragma unroll
    for (int k = 0; k < 64; k++) {
        float q[4], kk[4];
        #pragma unroll
        for (int i = 0; i < 4; i++) q[i] = Qs[ty * 4 + i][k];
        #pragma unroll
        for (int j = 0; j < 4; j++) kk[j] = Ks[tx * 4 + j][k];
        #pragma unroll
        for (int i = 0; i < 4; i++)
            #pragma unroll
            for (int j = 0; j < 4; j++)
                acc[i][j] = fmaf(q[i], kk[j], acc[i][j]);
    }

    const float scale = 0.125f; // 1/sqrt(64)
    #pragma unroll
    for (int i = 0; i < 4; i++) {
        int m = m0 + ty * 4 + i;
        size_t rowbase = ((size_t)bh * SEQ + m) * SEQ;
        #pragma unroll
        for (int j = 0; j < 4; j++) {
            int n = n0 + tx * 4 + j;
            float v = acc[i][j] * scale + mask[(size_t)b * SEQ + n] * (-1e9f);
            w[rowbase + n] = v;
        }
    }
}

// ---------------------------------------------------------------------------
// In-place row softmax over SEQ=2048. One block per row, 256 threads,
// 8 values per thread kept in registers.
// ---------------------------------------------------------------------------
__global__ void softmax_kernel(float* __restrict__ w)
{
    __shared__ float sred[32];
    size_t row = blockIdx.x;
    float* p = w + row * SEQ;
    int t = threadIdx.x;

    float v[8];
    float mx = -1e30f;
    #pragma unroll
    for (int i = 0; i < 8; i++) {
        v[i] = p[t + i * 256];
        mx = fmaxf(mx, v[i]);
    }
    // block max
    #pragma unroll
    for (int o = 16; o > 0; o >>= 1) mx = fmaxf(mx, __shfl_xor_sync(0xffffffff, mx, o));
    if ((t & 31) == 0) sred[t >> 5] = mx;
    __syncthreads();
    if (t < 32) {
        float m2 = (t < 8) ? sred[t] : -1e30f;
        #pragma unroll
        for (int o = 4; o > 0; o >>= 1) m2 = fmaxf(m2, __shfl_xor_sync(0xffffffff, m2, o));
        if (t == 0) sred[0] = m2;
    }
    __syncthreads();
    mx = sred[0];
    __syncthreads();

    float sum = 0.f;
    #pragma unroll
    for (int i = 0; i < 8; i++) {
        v[i] = __expf(v[i] - mx);
        sum += v[i];
    }
    #pragma unroll
    for (int o = 16; o > 0; o >>= 1) sum += __shfl_xor_sync(0xffffffff, sum, o);
    if ((t & 31) == 0) sred[t >> 5] = sum;
    __syncthreads();
    if (t < 32) {
        float s2 = (t < 8) ? sred[t] : 0.f;
        #pragma unroll
        for (int o = 4; o > 0; o >>= 1) s2 += __shfl_xor_sync(0xffffffff, s2, o);
        if (t == 0) sred[0] = s2;
    }
    __syncthreads();
    float inv = 1.0f / sred[0];

    #pragma unroll
    for (int i = 0; i < 8; i++) p[t + i * 256] = v[i] * inv;
}

// ---------------------------------------------------------------------------
// AV: for each (b,h): O[2048,64] = w[2048,2048] @ Vh[2048,64]
// Block: 64 rows x 64 cols (full depth). BK=32.
// Output written into [B,S,H*D] layout.
// ---------------------------------------------------------------------------
__global__ void av_kernel(const float* __restrict__ w,
                          const float* __restrict__ Vh,
                          float* __restrict__ attn)
{
    __shared__ float Ws[64][33];
    __shared__ float Vs[32][65];

    int tx = threadIdx.x, ty = threadIdx.y;
    int tid = ty * 16 + tx;
    int m0 = blockIdx.x * 64;
    int bh = blockIdx.y;
    int b  = bh / NHEADS;
    int h  = bh % NHEADS;

    const float* wb = w + (size_t)bh * SEQ * SEQ;
    const float* Vb = Vh + (size_t)bh * SEQ * DEPTH;

    float acc[4][4] = {};

    for (int k0 = 0; k0 < SEQ; k0 += 32) {
        // w tile 64x32 (2048/256 = 8 each)
        #pragma unroll
        for (int i = 0; i < 8; i++) {
            int e = tid + i * 256;
            int r = e >> 5, c = e & 31;
            Ws[r][c] = wb[(size_t)(m0 + r) * SEQ + k0 + c];
        }
        // v tile 32x64
        #pragma unroll
        for (int i = 0; i < 8; i++) {
            int e = tid + i * 256;
            int r = e >> 6, c = e & 63;
            Vs[r][c] = Vb[(size_t)(k0 + r) * DEPTH + c];
        }
        __syncthreads();

        #pragma unroll
        for (int k = 0; k < 32; k++) {
            float a[4], vv[4];
            #pragma unroll
            for (int i = 0; i < 4; i++) a[i] = Ws[ty * 4 + i][k];
            #pragma unroll
            for (int j = 0; j < 4; j++) vv[j] = Vs[k][tx * 4 + j];
            #pragma unroll
            for (int i = 0; i < 4; i++)
                #pragma unroll
                for (int j = 0; j < 4; j++)
                    acc[i][j] = fmaf(a[i], vv[j], acc[i][j]);
        }
        __syncthreads();
    }

    #pragma unroll
    for (int i = 0; i < 4; i++) {
        int s = m0 + ty * 4 + i;
        #pragma unroll
        for (int j = 0; j < 4; j++) {
            int d = tx * 4 + j;
            attn[((size_t)b * SEQ + s) * DMODEL + h * DEPTH + d] = acc[i][j];
        }
    }
}

// ---------------------------------------------------------------------------
extern "C" void kernel_launch(void* const* d_in, const int* in_sizes, int n_in,
                              void* d_out, int out_size)
{
    const float* q    = (const float*)d_in[0];
    const float* k    = (const float*)d_in[1];
    const float* v    = (const float*)d_in[2];
    const float* mask = (const float*)d_in[3];
    const float* Wq   = (const float*)d_in[4];
    const float* bq   = (const float*)d_in[5];
    const float* Wk   = (const float*)d_in[6];
    const float* bk   = (const float*)d_in[7];
    const float* Wv   = (const float*)d_in[8];
    const float* bv   = (const float*)d_in[9];
    const float* Wo   = (const float*)d_in[10];
    const float* bo   = (const float*)d_in[11];

    float* out_main = (float*)d_out;                                   // [2,2048,1024]
    float* out_w    = (float*)d_out + (size_t)BS * SEQ * DMODEL;       // [2,16,2048,2048]

    float *Qh, *Kh, *Vh, *attn;
    cudaGetSymbolAddress((void**)&Qh,   g_Qh);
    cudaGetSymbolAddress((void**)&Kh,   g_Kh);
    cudaGetSymbolAddress((void**)&Vh,   g_Vh);
    cudaGetSymbolAddress((void**)&attn, g_attn);

    const int M = BS * SEQ, N = DMODEL, K = DMODEL;
    dim3 thr(16, 16);
    dim3 gProj(N / 64, M / 64);

    gemm_proj_kernel<<<gProj, thr>>>(q, Wq, bq, Qh, M, N, K, 1);
    gemm_proj_kernel<<<gProj, thr>>>(k, Wk, bk, Kh, M, N, K, 1);
    gemm_proj_kernel<<<gProj, thr>>>(v, Wv, bv, Vh, M, N, K, 1);

    dim3 gScores(SEQ / 64, SEQ / 64, BH);
    scores_kernel<<<gScores, thr>>>(Qh, Kh, mask, out_w);

    softmax_kernel<<<BH * SEQ, 256>>>(out_w);

    dim3 gAV(SEQ / 64, BH);
    av_kernel<<<gAV, thr>>>(out_w, Vh, attn);

    gemm_proj_kernel<<<gProj, thr>>>(attn, Wo, bo, out_main, M, N, K, 0);
}

// round 2
// speedup vs baseline: 1.3287x; 1.3287x over previous
#include <cuda_runtime.h>
#include <cstdint>

#define BS 2
#define SEQ 2048
#define DMODEL 1024
#define NHEADS 16
#define DEPTH 64
#define BH (BS*NHEADS)

// Scratch (allocation-free rule: __device__ globals)
__device__ float g_Qh[BH * SEQ * DEPTH];   // [B,H,S,D]
__device__ float g_Kh[BH * SEQ * DEPTH];
__device__ float g_Vh[BH * SEQ * DEPTH];
__device__ float g_attn[BS * SEQ * DMODEL]; // [B,S,H*D] pre-Wo

// ---------------------------------------------------------------------------
// Fused QKV projection GEMM: for z in {0,1,2}:
//   out_z[M,N] = in_z[M,K] @ W_z[K,N] + b_z   (written head-split [B,H,S,D])
// 128x128 tile, BK=16, 256 threads, 8x8 per thread, reg prefetch.
// ---------------------------------------------------------------------------
__global__ void __launch_bounds__(256) gemm_qkv_kernel(
    const float* __restrict__ q, const float* __restrict__ k,
    const float* __restrict__ v,
    const float* __restrict__ Wq, const float* __restrict__ bq,
    const float* __restrict__ Wk, const float* __restrict__ bk,
    const float* __restrict__ Wv, const float* __restrict__ bv,
    float* __restrict__ Qh, float* __restrict__ Kh, float* __restrict__ Vh)
{
    const int M = BS * SEQ, N = DMODEL, K = DMODEL;
    __shared__ float As[16][132];
    __shared__ float Bs[16][132];

    int z = blockIdx.z;
    const float* A    = (z == 0) ? q  : (z == 1) ? k  : v;
    const float* W    = (z == 0) ? Wq : (z == 1) ? Wk : Wv;
    const float* bias = (z == 0) ? bq : (z == 1) ? bk : bv;
    float* out        = (z == 0) ? Qh : (z == 1) ? Kh : Vh;

    int tx = threadIdx.x, ty = threadIdx.y;
    int tid = ty * 16 + tx;
    int m0 = blockIdx.y * 128;
    int n0 = blockIdx.x * 128;

    // load-index precompute
    int ea0 = tid, ea1 = tid + 256;           // float4 ids for A tile (512)
    int ar0 = ea0 >> 2, ac0 = (ea0 & 3) * 4;
    int ar1 = ea1 >> 2, ac1 = (ea1 & 3) * 4;
    int br0 = ea0 >> 5, bc0 = (ea0 & 31) * 4;
    int br1 = ea1 >> 5, bc1 = (ea1 & 31) * 4;

    float4 ra0, ra1, rb0, rb1;
    // prefetch tile k0=0
    ra0 = *(const float4*)&A[(size_t)(m0 + ar0) * K + ac0];
    ra1 = *(const float4*)&A[(size_t)(m0 + ar1) * K + ac1];
    rb0 = *(const float4*)&W[(size_t)(br0) * N + n0 + bc0];
    rb1 = *(const float4*)&W[(size_t)(br1) * N + n0 + bc1];

    float acc[8][8] = {};

    for (int k0 = 0; k0 < K; k0 += 16) {
        // store current tile (A transposed)
        As[ac0 + 0][ar0] = ra0.x; As[ac0 + 1][ar0] = ra0.y;
        As[ac0 + 2][ar0] = ra0.z; As[ac0 + 3][ar0] = ra0.w;
        As[ac1 + 0][ar1] = ra1.x; As[ac1 + 1][ar1] = ra1.y;
        As[ac1 + 2][ar1] = ra1.z; As[ac1 + 3][ar1] = ra1.w;
        *(float4*)&Bs[br0][bc0] = rb0;
        *(float4*)&Bs[br1][bc1] = rb1;
        __syncthreads();

        // prefetch next
        if (k0 + 16 < K) {
            ra0 = *(const float4*)&A[(size_t)(m0 + ar0) * K + k0 + 16 + ac0];
            ra1 = *(const float4*)&A[(size_t)(m0 + ar1) * K + k0 + 16 + ac1];
            rb0 = *(const float4*)&W[(size_t)(k0 + 16 + br0) * N + n0 + bc0];
            rb1 = *(const float4*)&W[(size_t)(k0 + 16 + br1) * N + n0 + bc1];
        }

        #pragma unroll
        for (int kk = 0; kk < 16; kk++) {
            float4 a0 = *(float4*)&As[kk][ty * 4];
            float4 a1 = *(float4*)&As[kk][64 + ty * 4];
            float4 b0 = *(float4*)&Bs[kk][tx * 4];
            float4 b1 = *(float4*)&Bs[kk][64 + tx * 4];
            float a[8] = {a0.x,a0.y,a0.z,a0.w,a1.x,a1.y,a1.z,a1.w};
            float b[8] = {b0.x,b0.y,b0.z,b0.w,b1.x,b1.y,b1.z,b1.w};
            #pragma unroll
            for (int i = 0; i < 8; i++)
                #pragma unroll
                for (int j = 0; j < 8; j++)
                    acc[i][j] = fmaf(a[i], b[j], acc[i][j]);
        }
        __syncthreads();
    }

    // epilogue: bias + head-split store [B,H,S,D]
    #pragma unroll
    for (int i = 0; i < 8; i++) {
        int m = m0 + ((i < 4) ? (ty * 4 + i) : (64 + ty * 4 + i - 4));
        int b_ = m >> 11, s = m & 2047;
        #pragma unroll
        for (int j = 0; j < 8; j++) {
            int n = n0 + ((j < 4) ? (tx * 4 + j) : (64 + tx * 4 + j - 4));
            int h = n >> 6, d = n & 63;
            out[(((size_t)(b_ * NHEADS + h) * SEQ) + s) * DEPTH + d] =
                acc[i][j] + bias[n];
        }
    }
}

// ---------------------------------------------------------------------------
// Output projection: C[M,N] = A[M,K] @ W[K,N] + bias (row-major out)
// Same tiling as above.
// ---------------------------------------------------------------------------
__global__ void __launch_bounds__(256) gemm_out_kernel(
    const float* __restrict__ A, const float* __restrict__ W,
    const float* __restrict__ bias, float* __restrict__ out)
{
    const int M = BS * SEQ, N = DMODEL, K = DMODEL;
    __shared__ float As[16][132];
    __shared__ float Bs[16][132];

    int tx = threadIdx.x, ty = threadIdx.y;
    int tid = ty * 16 + tx;
    int m0 = blockIdx.y * 128;
    int n0 = blockIdx.x * 128;

    int ea0 = tid, ea1 = tid + 256;
    int ar0 = ea0 >> 2, ac0 = (ea0 & 3) * 4;
    int ar1 = ea1 >> 2, ac1 = (ea1 & 3) * 4;
    int br0 = ea0 >> 5, bc0 = (ea0 & 31) * 4;
    int br1 = ea1 >> 5, bc1 = (ea1 & 31) * 4;

    float4 ra0, ra1, rb0, rb1;
    ra0 = *(const float4*)&A[(size_t)(m0 + ar0) * K + ac0];
    ra1 = *(const float4*)&A[(size_t)(m0 + ar1) * K + ac1];
    rb0 = *(const float4*)&W[(size_t)(br0) * N + n0 + bc0];
    rb1 = *(const float4*)&W[(size_t)(br1) * N + n0 + bc1];

    float acc[8][8] = {};

    for (int k0 = 0; k0 < K; k0 += 16) {
        As[ac0 + 0][ar0] = ra0.x; As[ac0 + 1][ar0] = ra0.y;
        As[ac0 + 2][ar0] = ra0.z; As[ac0 + 3][ar0] = ra0.w;
        As[ac1 + 0][ar1] = ra1.x; As[ac1 + 1][ar1] = ra1.y;
        As[ac1 + 2][ar1] = ra1.z; As[ac1 + 3][ar1] = ra1.w;
        *(float4*)&Bs[br0][bc0] = rb0;
        *(float4*)&Bs[br1][bc1] = rb1;
        __syncthreads();

        if (k0 + 16 < K) {
            ra0 = *(const float4*)&A[(size_t)(m0 + ar0) * K + k0 + 16 + ac0];
            ra1 = *(const float4*)&A[(size_t)(m0 + ar1) * K + k0 + 16 + ac1];
            rb0 = *(const float4*)&W[(size_t)(k0 + 16 + br0) * N + n0 + bc0];
            rb1 = *(const float4*)&W[(size_t)(k0 + 16 + br1) * N + n0 + bc1];
        }

        #pragma unroll
        for (int kk = 0; kk < 16; kk++) {
            float4 a0 = *(float4*)&As[kk][ty * 4];
            float4 a1 = *(float4*)&As[kk][64 + ty * 4];
            float4 b0 = *(float4*)&Bs[kk][tx * 4];
            float4 b1 = *(float4*)&Bs[kk][64 + tx * 4];
            float a[8] = {a0.x,a0.y,a0.z,a0.w,a1.x,a1.y,a1.z,a1.w};
            float b[8] = {b0.x,b0.y,b0.z,b0.w,b1.x,b1.y,b1.z,b1.w};
            #pragma unroll
            for (int i = 0; i < 8; i++)
                #pragma unroll
                for (int j = 0; j < 8; j++)
                    acc[i][j] = fmaf(a[i], b[j], acc[i][j]);
        }
        __syncthreads();
    }

    #pragma unroll
    for (int i = 0; i < 8; i++) {
        int m = m0 + ((i < 4) ? (ty * 4 + i) : (64 + ty * 4 + i - 4));
        #pragma unroll
        for (int j = 0; j < 8; j++) {
            int n = n0 + ((j < 4) ? (tx * 4 + j) : (64 + tx * 4 + j - 4));
            out[(size_t)m * N + n] = acc[i][j] + bias[n];
        }
    }
}

// ---------------------------------------------------------------------------
// Scores: per (b,h): S = Qh @ Kh^T /8 + mask*(-1e9). 128x128 tile, BK=32 (x2).
// ---------------------------------------------------------------------------
__global__ void __launch_bounds__(256) scores_kernel(
    const float* __restrict__ Qh, const float* __restrict__ Kh,
    const float* __restrict__ mask, float* __restrict__ w)
{
    __shared__ float Qs[32][132];
    __shared__ float Ks[32][132];

    int tx = threadIdx.x, ty = threadIdx.y;
    int tid = ty * 16 + tx;
    int m0 = blockIdx.y * 128;
    int n0 = blockIdx.x * 128;
    int bh = blockIdx.z;
    int b  = bh / NHEADS;

    const float* Qb = Qh + (size_t)bh * SEQ * DEPTH;
    const float* Kb = Kh + (size_t)bh * SEQ * DEPTH;

    float acc[8][8] = {};

    for (int d0 = 0; d0 < DEPTH; d0 += 32) {
        // load 128x32 tiles, transposed to [d][m]
        #pragma unroll
        for (int i = 0; i < 4; i++) {
            int e = tid + i * 256;          // float4 id 0..1023
            int r = e >> 3, cg = (e & 7) * 4;
            float4 fq = *(const float4*)&Qb[(size_t)(m0 + r) * DEPTH + d0 + cg];
            float4 fk = *(const float4*)&Kb[(size_t)(n0 + r) * DEPTH + d0 + cg];
            Qs[cg + 0][r] = fq.x; Qs[cg + 1][r] = fq.y;
            Qs[cg + 2][r] = fq.z; Qs[cg + 3][r] = fq.w;
            Ks[cg + 0][r] = fk.x; Ks[cg + 1][r] = fk.y;
            Ks[cg + 2][r] = fk.z; Ks[cg + 3][r] = fk.w;
        }
        __syncthreads();

        #pragma unroll
        for (int kk = 0; kk < 32; kk++) {
            float4 a0 = *(float4*)&Qs[kk][ty * 4];
            float4 a1 = *(float4*)&Qs[kk][64 + ty * 4];
            float4 b0 = *(float4*)&Ks[kk][tx * 4];
            float4 b1 = *(float4*)&Ks[kk][64 + tx * 4];
            float a[8] = {a0.x,a0.y,a0.z,a0.w,a1.x,a1.y,a1.z,a1.w};
            float bb[8] = {b0.x,b0.y,b0.z,b0.w,b1.x,b1.y,b1.z,b1.w};
            #pragma unroll
            for (int i = 0; i < 8; i++)
                #pragma unroll
                for (int j = 0; j < 8; j++)
                    acc[i][j] = fmaf(a[i], bb[j], acc[i][j]);
        }
        __syncthreads();
    }

    const float scale = 0.125f;
    #pragma unroll
    for (int i = 0; i < 8; i++) {
        int m = m0 + ((i < 4) ? (ty * 4 + i) : (64 + ty * 4 + i - 4));
        size_t rowbase = ((size_t)bh * SEQ + m) * SEQ;
        #pragma unroll
        for (int jg = 0; jg < 2; jg++) {
            int n = n0 + ((jg == 0) ? (tx * 4) : (64 + tx * 4));
            float4 o;
            o.x = acc[i][jg*4+0] * scale + mask[(size_t)b * SEQ + n + 0] * (-1e9f);
            o.y = acc[i][jg*4+1] * scale + mask[(size_t)b * SEQ + n + 1] * (-1e9f);
            o.z = acc[i][jg*4+2] * scale + mask[(size_t)b * SEQ + n + 2] * (-1e9f);
            o.w = acc[i][jg*4+3] * scale + mask[(size_t)b * SEQ + n + 3] * (-1e9f);
            *(float4*)&w[rowbase + n] = o;
        }
    }
}

// ---------------------------------------------------------------------------
// In-place row softmax over SEQ=2048 (float4, 256 thr, 8 vals/thread)
// ---------------------------------------------------------------------------
__global__ void __launch_bounds__(256) softmax_kernel(float* __restrict__ w)
{
    __shared__ float sred[32];
    size_t row = blockIdx.x;
    float4* p = (float4*)(w + row * SEQ);
    int t = threadIdx.x;

    float4 v0 = p[t];
    float4 v1 = p[t + 256];
    float mx = fmaxf(fmaxf(fmaxf(v0.x, v0.y), fmaxf(v0.z, v0.w)),
                     fmaxf(fmaxf(v1.x, v1.y), fmaxf(v1.z, v1.w)));
    #pragma unroll
    for (int o = 16; o > 0; o >>= 1) mx = fmaxf(mx, __shfl_xor_sync(0xffffffff, mx, o));
    if ((t & 31) == 0) sred[t >> 5] = mx;
    __syncthreads();
    if (t < 32) {
        float m2 = (t < 8) ? sred[t] : -1e30f;
        #pragma unroll
        for (int o = 4; o > 0; o >>= 1) m2 = fmaxf(m2, __shfl_xor_sync(0xffffffff, m2, o));
        if (t == 0) sred[0] = m2;
    }
    __syncthreads();
    mx = sred[0];
    __syncthreads();

    v0.x = __expf(v0.x - mx); v0.y = __expf(v0.y - mx);
    v0.z = __expf(v0.z - mx); v0.w = __expf(v0.w - mx);
    v1.x = __expf(v1.x - mx); v1.y = __expf(v1.y - mx);
    v1.z = __expf(v1.z - mx); v1.w = __expf(v1.w - mx);
    float sum = v0.x + v0.y + v0.z + v0.w + v1.x + v1.y + v1.z + v1.w;
    #pragma unroll
    for (int o = 16; o > 0; o >>= 1) sum += __shfl_xor_sync(0xffffffff, sum, o);
    if ((t & 31) == 0) sred[t >> 5] = sum;
    __syncthreads();
    if (t < 32) {
        float s2 = (t < 8) ? sred[t] : 0.f;
        #pragma unroll
        for (int o = 4; o > 0; o >>= 1) s2 += __shfl_xor_sync(0xffffffff, s2, o);
        if (t == 0) sred[0] = s2;
    }
    __syncthreads();
    float inv = 1.0f / sred[0];

    v0.x *= inv; v0.y *= inv; v0.z *= inv; v0.w *= inv;
    v1.x *= inv; v1.y *= inv; v1.z *= inv; v1.w *= inv;
    p[t] = v0;
    p[t + 256] = v1;
}

// ---------------------------------------------------------------------------
// AV: per (b,h): O[2048,64] = w @ Vh. 128x64 tile, BK=32, 8x4 per thread.
// ---------------------------------------------------------------------------
__global__ void __launch_bounds__(256) av_kernel(
    const float* __restrict__ w, const float* __restrict__ Vh,
    float* __restrict__ attn)
{
    __shared__ float Ws[32][132];
    __shared__ float Vs[32][68];

    int tx = threadIdx.x, ty = threadIdx.y;
    int tid = ty * 16 + tx;
    int m0 = blockIdx.x * 128;
    int bh = blockIdx.y;
    int b  = bh / NHEADS;
    int h  = bh % NHEADS;

    const float* wb = w + (size_t)bh * SEQ * SEQ;
    const float* Vb = Vh + (size_t)bh * SEQ * DEPTH;

    float acc[8][4] = {};

    for (int k0 = 0; k0 < SEQ; k0 += 32) {
        // w tile 128x32, transposed to Ws[k][m]
        #pragma unroll
        for (int i = 0; i < 4; i++) {
            int e = tid + i * 256;
            int r = e >> 3, cg = (e & 7) * 4;
            float4 f = *(const float4*)&wb[(size_t)(m0 + r) * SEQ + k0 + cg];
            Ws[cg + 0][r] = f.x; Ws[cg + 1][r] = f.y;
            Ws[cg + 2][r] = f.z; Ws[cg + 3][r] = f.w;
        }
        // V tile 32x64
        #pragma unroll
        for (int i = 0; i < 2; i++) {
            int e = tid + i * 256;
            int r = e >> 4, cg = (e & 15) * 4;
            *(float4*)&Vs[r][cg] = *(const float4*)&Vb[(size_t)(k0 + r) * DEPTH + cg];
        }
        __syncthreads();

        #pragma unroll
        for (int kk = 0; kk < 32; kk++) {
            float4 a0 = *(float4*)&Ws[kk][ty * 4];
            float4 a1 = *(float4*)&Ws[kk][64 + ty * 4];
            float4 b0 = *(float4*)&Vs[kk][tx * 4];
            float a[8] = {a0.x,a0.y,a0.z,a0.w,a1.x,a1.y,a1.z,a1.w};
            float bb[4] = {b0.x,b0.y,b0.z,b0.w};
            #pragma unroll
            for (int i = 0; i < 8; i++)
                #pragma unroll
                for (int j = 0; j < 4; j++)
                    acc[i][j] = fmaf(a[i], bb[j], acc[i][j]);
        }
        __syncthreads();
    }

    #pragma unroll
    for (int i = 0; i < 8; i++) {
        int s = m0 + ((i < 4) ? (ty * 4 + i) : (64 + ty * 4 + i - 4));
        float4 o = {acc[i][0], acc[i][1], acc[i][2], acc[i][3]};
        *(float4*)&attn[((size_t)b * SEQ + s) * DMODEL + h * DEPTH + tx * 4] = o;
    }
}

// ---------------------------------------------------------------------------
extern "C" void kernel_launch(void* const* d_in, const int* in_sizes, int n_in,
                              void* d_out, int out_size)
{
    const float* q    = (const float*)d_in[0];
    const float* k    = (const float*)d_in[1];
    const float* v    = (const float*)d_in[2];
    const float* mask = (const float*)d_in[3];
    const float* Wq   = (const float*)d_in[4];
    const float* bq   = (const float*)d_in[5];
    const float* Wk   = (const float*)d_in[6];
    const float* bk   = (const float*)d_in[7];
    const float* Wv   = (const float*)d_in[8];
    const float* bv   = (const float*)d_in[9];
    const float* Wo   = (const float*)d_in[10];
    const float* bo   = (const float*)d_in[11];

    float* out_main = (float*)d_out;                                   // [2,2048,1024]
    float* out_w    = (float*)d_out + (size_t)BS * SEQ * DMODEL;       // [2,16,2048,2048]

    float *Qh, *Kh, *Vh, *attn;
    cudaGetSymbolAddress((void**)&Qh,   g_Qh);
    cudaGetSymbolAddress((void**)&Kh,   g_Kh);
    cudaGetSymbolAddress((void**)&Vh,   g_Vh);
    cudaGetSymbolAddress((void**)&attn, g_attn);

    dim3 thr(16, 16);

    dim3 gQKV(DMODEL / 128, (BS * SEQ) / 128, 3);     // 8 x 32 x 3
    gemm_qkv_kernel<<<gQKV, thr>>>(q, k, v, Wq, bq, Wk, bk, Wv, bv, Qh, Kh, Vh);

    dim3 gScores(SEQ / 128, SEQ / 128, BH);            // 16 x 16 x 32
    scores_kernel<<<gScores, thr>>>(Qh, Kh, mask, out_w);

    softmax_kernel<<<BH * SEQ, 256>>>(out_w);

    dim3 gAV(SEQ / 128, BH);                           // 16 x 32
    av_kernel<<<gAV, thr>>>(out_w, Vh, attn);

    dim3 gOut(DMODEL / 128, (BS * SEQ) / 128);         // 8 x 32
    gemm_out_kernel<<<gOut, thr>>>(attn, Wo, bo, out_main);
}

// round 6
// speedup vs baseline: 1.8275x; 1.3754x over previous
#include <cuda_runtime.h>
#include <cuda_bf16.h>
#include <cstdint>

#define BS 2
#define SEQ 2048
#define DMODEL 1024
#define NHEADS 16
#define DEPTH 64
#define BH (BS*NHEADS)
#define MTOT (BS*SEQ)
#define SA 40   // smem row stride (bf16 elems): (20r+tc)%32 distinct -> conflict-free

// ---------------------------------------------------------------------------
// Device scratch (allocation-free rule)
// ---------------------------------------------------------------------------
__device__ __nv_bfloat16 g_xhi[3ULL*MTOT*DMODEL], g_xlo[3ULL*MTOT*DMODEL];
__device__ __nv_bfloat16 g_wThi[4ULL*DMODEL*DMODEL], g_wTlo[4ULL*DMODEL*DMODEL]; // [z][n][k]
__device__ __nv_bfloat16 g_qhi[(size_t)BH*SEQ*DEPTH], g_qlo[(size_t)BH*SEQ*DEPTH];
__device__ __nv_bfloat16 g_khi[(size_t)BH*SEQ*DEPTH], g_klo[(size_t)BH*SEQ*DEPTH];
__device__ __nv_bfloat16 g_vhi[(size_t)BH*SEQ*DEPTH], g_vlo[(size_t)BH*SEQ*DEPTH];   // [bh][s][d]
__device__ __nv_bfloat16 g_vThi[(size_t)BH*DEPTH*SEQ], g_vTlo[(size_t)BH*DEPTH*SEQ]; // [bh][d][s]
__device__ __nv_bfloat16 g_whi[(size_t)BH*SEQ*SEQ], g_wlo[(size_t)BH*SEQ*SEQ];
__device__ __nv_bfloat16 g_athi[(size_t)MTOT*DMODEL], g_atlo[(size_t)MTOT*DMODEL];

// ---------------------------------------------------------------------------
__device__ __forceinline__ void split_bf16(float x, __nv_bfloat16& h, __nv_bfloat16& l) {
    h = __float2bfloat16(x);
    l = __float2bfloat16(x - __bfloat162float(h));
}

__device__ __forceinline__ void mma_bf16(float c[4],
        uint32_t a0, uint32_t a1, uint32_t a2, uint32_t a3,
        uint32_t b0, uint32_t b1) {
    asm volatile(
        "mma.sync.aligned.m16n8k16.row.col.f32.bf16.bf16.f32 "
        "{%0,%1,%2,%3}, {%4,%5,%6,%7}, {%8,%9}, {%0,%1,%2,%3};"
        : "+f"(c[0]), "+f"(c[1]), "+f"(c[2]), "+f"(c[3])
        : "r"(a0), "r"(a1), "r"(a2), "r"(a3), "r"(b0), "r"(b1));
}

__device__ __forceinline__ uint32_t ld32(const __nv_bfloat16* p) {
    return *reinterpret_cast<const uint32_t*>(p);
}

// ---------------------------------------------------------------------------
// Prep: inputs -> bf16 hi/lo
// ---------------------------------------------------------------------------
__global__ void prep_inputs(const float* __restrict__ q, const float* __restrict__ k,
                            const float* __restrict__ v) {
    const size_t n1 = (size_t)MTOT * DMODEL;
    const size_t n1v = n1 / 4;
    size_t total = 3 * n1v;
    for (size_t i = blockIdx.x * (size_t)blockDim.x + threadIdx.x; i < total;
         i += (size_t)gridDim.x * blockDim.x) {
        size_t seg = i / n1v;
        size_t off = (i - seg * n1v) * 4;
        const float* src = (seg == 0) ? q : (seg == 1) ? k : v;
        float4 f = *(const float4*)(src + off);
        size_t base = seg * n1 + off;
        __nv_bfloat16 h, l;
        split_bf16(f.x, h, l); g_xhi[base+0] = h; g_xlo[base+0] = l;
        split_bf16(f.y, h, l); g_xhi[base+1] = h; g_xlo[base+1] = l;
        split_bf16(f.z, h, l); g_xhi[base+2] = h; g_xlo[base+2] = l;
        split_bf16(f.w, h, l); g_xhi[base+3] = h; g_xlo[base+3] = l;
    }
}

// Prep: W[k][n] -> wT[z][n][k] hi/lo
__global__ void prep_weights(const float* __restrict__ Wq, const float* __restrict__ Wk,
                             const float* __restrict__ Wv, const float* __restrict__ Wo) {
    __shared__ float t[32][33];
    int z = blockIdx.z;
    const float* W = (z == 0) ? Wq : (z == 1) ? Wk : (z == 2) ? Wv : Wo;
    int n0 = blockIdx.x * 32, k0 = blockIdx.y * 32;
    int tx = threadIdx.x, ty = threadIdx.y;   // 32 x 8
    #pragma unroll
    for (int i = 0; i < 4; i++)
        t[ty + 8*i][tx] = W[(size_t)(k0 + ty + 8*i) * DMODEL + n0 + tx];
    __syncthreads();
    #pragma unroll
    for (int i = 0; i < 4; i++) {
        float x = t[tx][ty + 8*i];
        __nv_bfloat16 h, l; split_bf16(x, h, l);
        size_t idx = ((size_t)z * DMODEL + (n0 + ty + 8*i)) * DMODEL + k0 + tx;
        g_wThi[idx] = h; g_wTlo[idx] = l;
    }
}

// ---------------------------------------------------------------------------
// QKV projection: C[4096,1024] = X@W + b.  mma.sync bf16, 3-term split.
// Block tile 128x128, 8 warps (2m x 4n), warp tile 64x32, BK=32.
// z<2 -> Qh/Kh [bh][s][d] split; z==2 -> V [bh][s][d] split (transposed later).
// ---------------------------------------------------------------------------
__global__ void __launch_bounds__(256) proj_qkv_kernel(
        const float* __restrict__ bq, const float* __restrict__ bk,
        const float* __restrict__ bv) {
    __shared__ __nv_bfloat16 Ash[128*SA], Asl[128*SA], Bsh[128*SA], Bsl[128*SA];
    int tid = threadIdx.x, lane = tid & 31, warp = tid >> 5;
    int g = lane >> 2, tc = lane & 3;
    int wm = (warp & 1) * 64, wn = (warp >> 1) * 32;
    int z = blockIdx.z;
    int m0 = blockIdx.y * 128, n0 = blockIdx.x * 128;

    const __nv_bfloat16* Ahi = g_xhi + (size_t)z * MTOT * DMODEL;
    const __nv_bfloat16* Alo = g_xlo + (size_t)z * MTOT * DMODEL;
    const __nv_bfloat16* Bhi = g_wThi + (size_t)z * DMODEL * DMODEL;
    const __nv_bfloat16* Blo = g_wTlo + (size_t)z * DMODEL * DMODEL;
    const float* bias = (z == 0) ? bq : (z == 1) ? bk : bv;

    float acc[4][4][4] = {};

    for (int kt = 0; kt < DMODEL; kt += 32) {
        #pragma unroll
        for (int i = 0; i < 2; i++) {
            int e = tid + i * 256;
            int r = e >> 2, c8 = (e & 3) * 8;
            size_t ga = (size_t)(m0 + r) * DMODEL + kt + c8;
            size_t gb = (size_t)(n0 + r) * DMODEL + kt + c8;
            *(uint4*)&Ash[r*SA + c8] = *(const uint4*)&Ahi[ga];
            *(uint4*)&Asl[r*SA + c8] = *(const uint4*)&Alo[ga];
            *(uint4*)&Bsh[r*SA + c8] = *(const uint4*)&Bhi[gb];
            *(uint4*)&Bsl[r*SA + c8] = *(const uint4*)&Blo[gb];
        }
        __syncthreads();
        #pragma unroll
        for (int kk = 0; kk < 32; kk += 16) {
            uint32_t ah[4][4], al[4][4];
            #pragma unroll
            for (int mf = 0; mf < 4; mf++) {
                int r0 = (wm + mf*16 + g) * SA + kk + tc*2;
                int r1 = r0 + 8*SA;
                ah[mf][0] = ld32(&Ash[r0]);   ah[mf][1] = ld32(&Ash[r1]);
                ah[mf][2] = ld32(&Ash[r0+8]); ah[mf][3] = ld32(&Ash[r1+8]);
                al[mf][0] = ld32(&Asl[r0]);   al[mf][1] = ld32(&Asl[r1]);
                al[mf][2] = ld32(&Asl[r0+8]); al[mf][3] = ld32(&Asl[r1+8]);
            }
            #pragma unroll
            for (int nf = 0; nf < 4; nf++) {
                int q0 = (wn + nf*8 + g) * SA + kk + tc*2;
                uint32_t bh0 = ld32(&Bsh[q0]), bh1 = ld32(&Bsh[q0+8]);
                uint32_t bl0 = ld32(&Bsl[q0]), bl1 = ld32(&Bsl[q0+8]);
                #pragma unroll
                for (int mf = 0; mf < 4; mf++) {
                    mma_bf16(acc[mf][nf], ah[mf][0], ah[mf][1], ah[mf][2], ah[mf][3], bh0, bh1);
                    mma_bf16(acc[mf][nf], ah[mf][0], ah[mf][1], ah[mf][2], ah[mf][3], bl0, bl1);
                    mma_bf16(acc[mf][nf], al[mf][0], al[mf][1], al[mf][2], al[mf][3], bh0, bh1);
                }
            }
        }
        __syncthreads();
    }

    __nv_bfloat16 *Dh, *Dl;
    if (z == 0) { Dh = g_qhi; Dl = g_qlo; }
    else if (z == 1) { Dh = g_khi; Dl = g_klo; }
    else { Dh = g_vhi; Dl = g_vlo; }

    #pragma unroll
    for (int mf = 0; mf < 4; mf++) {
        #pragma unroll
        for (int rr = 0; rr < 2; rr++) {
            int m = m0 + wm + mf*16 + g + rr*8;
            int b = m >> 11, s = m & (SEQ-1);
            #pragma unroll
            for (int nf = 0; nf < 4; nf++) {
                int n = n0 + wn + nf*8 + tc*2;
                int h = n >> 6, d = n & 63;
                float v0 = acc[mf][nf][rr*2+0] + bias[n];
                float v1 = acc[mf][nf][rr*2+1] + bias[n+1];
                __nv_bfloat16 h0, l0, h1, l1;
                split_bf16(v0, h0, l0); split_bf16(v1, h1, l1);
                size_t base = ((size_t)(b*NHEADS + h) * SEQ + s) * DEPTH + d;
                __nv_bfloat162 hp; hp.x = h0; hp.y = h1;
                __nv_bfloat162 lp; lp.x = l0; lp.y = l1;
                *(__nv_bfloat162*)&Dh[base] = hp;
                *(__nv_bfloat162*)&Dl[base] = lp;
            }
        }
    }
}

// ---------------------------------------------------------------------------
// Transpose V [bh][s][d] -> vT [bh][d][s] (hi/lo)
// ---------------------------------------------------------------------------
__global__ void __launch_bounds__(256) transpose_v() {
    __shared__ __nv_bfloat16 th[64][66], tl[64][66];
    int bh = blockIdx.z, s0 = blockIdx.x * 64;
    int tid = threadIdx.x;
    #pragma unroll
    for (int i = 0; i < 8; i++) {
        int e = tid + i * 256;
        int r = e >> 5, c2 = (e & 31) * 2;
        size_t gsrc = ((size_t)bh * SEQ + s0 + r) * DEPTH + c2;
        *(uint32_t*)&th[r][c2] = *(const uint32_t*)&g_vhi[gsrc];
        *(uint32_t*)&tl[r][c2] = *(const uint32_t*)&g_vlo[gsrc];
    }
    __syncthreads();
    #pragma unroll
    for (int i = 0; i < 8; i++) {
        int e = tid + i * 256;
        int d = e >> 5, s2 = (e & 31) * 2;
        size_t gdst = ((size_t)bh * DEPTH + d) * SEQ + s0 + s2;
        __nv_bfloat162 ph; ph.x = th[s2][d]; ph.y = th[s2+1][d];
        __nv_bfloat162 pl; pl.x = tl[s2][d]; pl.y = tl[s2+1][d];
        *(__nv_bfloat162*)&g_vThi[gdst] = ph;
        *(__nv_bfloat162*)&g_vTlo[gdst] = pl;
    }
}

// ---------------------------------------------------------------------------
// Scores: per (b,h) S = Qh @ Kh^T / 8 + mask*(-1e9) -> fp32 w.
// Block tile 128x128, 8 warps, BK=32, K=64 (2 iters).
// ---------------------------------------------------------------------------
__global__ void __launch_bounds__(256) scores_kernel(
        const float* __restrict__ mask, float* __restrict__ w) {
    __shared__ __nv_bfloat16 Ash[128*SA], Asl[128*SA], Bsh[128*SA], Bsl[128*SA];
    int tid = threadIdx.x, lane = tid & 31, warp = tid >> 5;
    int g = lane >> 2, tc = lane & 3;
    int wm = (warp & 1) * 64, wn = (warp >> 1) * 32;
    int m0 = blockIdx.y * 128, n0 = blockIdx.x * 128;
    int bh = blockIdx.z, b = bh >> 4;

    const __nv_bfloat16* Ahi = g_qhi + (size_t)bh * SEQ * DEPTH;
    const __nv_bfloat16* Alo = g_qlo + (size_t)bh * SEQ * DEPTH;
    const __nv_bfloat16* Bhi = g_khi + (size_t)bh * SEQ * DEPTH;
    const __nv_bfloat16* Blo = g_klo + (size_t)bh * SEQ * DEPTH;

    float acc[4][4][4] = {};

    for (int kt = 0; kt < DEPTH; kt += 32) {
        #pragma unroll
        for (int i = 0; i < 2; i++) {
            int e = tid + i * 256;
            int r = e >> 2, c8 = (e & 3) * 8;
            size_t ga = (size_t)(m0 + r) * DEPTH + kt + c8;
            size_t gb = (size_t)(n0 + r) * DEPTH + kt + c8;
            *(uint4*)&Ash[r*SA + c8] = *(const uint4*)&Ahi[ga];
            *(uint4*)&Asl[r*SA + c8] = *(const uint4*)&Alo[ga];
            *(uint4*)&Bsh[r*SA + c8] = *(const uint4*)&Bhi[gb];
            *(uint4*)&Bsl[r*SA + c8] = *(const uint4*)&Blo[gb];
        }
        __syncthreads();
        #pragma unroll
        for (int kk = 0; kk < 32; kk += 16) {
            uint32_t ah[4][4], al[4][4];
            #pragma unroll
            for (int mf = 0; mf < 4; mf++) {
                int r0 = (wm + mf*16 + g) * SA + kk + tc*2;
                int r1 = r0 + 8*SA;
                ah[mf][0] = ld32(&Ash[r0]);   ah[mf][1] = ld32(&Ash[r1]);
                ah[mf][2] = ld32(&Ash[r0+8]); ah[mf][3] = ld32(&Ash[r1+8]);
                al[mf][0] = ld32(&Asl[r0]);   al[mf][1] = ld32(&Asl[r1]);
                al[mf][2] = ld32(&Asl[r0+8]); al[mf][3] = ld32(&Asl[r1+8]);
            }
            #pragma unroll
            for (int nf = 0; nf < 4; nf++) {
                int q0 = (wn + nf*8 + g) * SA + kk + tc*2;
                uint32_t bh0 = ld32(&Bsh[q0]), bh1 = ld32(&Bsh[q0+8]);
                uint32_t bl0 = ld32(&Bsl[q0]), bl1 = ld32(&Bsl[q0+8]);
                #pragma unroll
                for (int mf = 0; mf < 4; mf++) {
                    mma_bf16(acc[mf][nf], ah[mf][0], ah[mf][1], ah[mf][2], ah[mf][3], bh0, bh1);
                    mma_bf16(acc[mf][nf], ah[mf][0], ah[mf][1], ah[mf][2], ah[mf][3], bl0, bl1);
                    mma_bf16(acc[mf][nf], al[mf][0], al[mf][1], al[mf][2], al[mf][3], bh0, bh1);
                }
            }
        }
        __syncthreads();
    }

    #pragma unroll
    for (int mf = 0; mf < 4; mf++) {
        #pragma unroll
        for (int rr = 0; rr < 2; rr++) {
            int m = m0 + wm + mf*16 + g + rr*8;
            size_t rowb = ((size_t)bh * SEQ + m) * SEQ;
            #pragma unroll
            for (int nf = 0; nf < 4; nf++) {
                int n = n0 + wn + nf*8 + tc*2;
                float2 o;
                o.x = acc[mf][nf][rr*2+0] * 0.125f + mask[(size_t)b*SEQ + n] * (-1e9f);
                o.y = acc[mf][nf][rr*2+1] * 0.125f + mask[(size_t)b*SEQ + n + 1] * (-1e9f);
                *(float2*)&w[rowb + n] = o;
            }
        }
    }
}

// ---------------------------------------------------------------------------
// Softmax in place (fp32) + emit bf16 hi/lo copy for AV MMA
// ---------------------------------------------------------------------------
__global__ void __launch_bounds__(256) softmax_kernel(float* __restrict__ w) {
    __shared__ float sred[32];
    size_t row = blockIdx.x;
    float4* p = (float4*)(w + row * SEQ);
    int t = threadIdx.x;

    float4 v0 = p[t];
    float4 v1 = p[t + 256];
    float mx = fmaxf(fmaxf(fmaxf(v0.x, v0.y), fmaxf(v0.z, v0.w)),
                     fmaxf(fmaxf(v1.x, v1.y), fmaxf(v1.z, v1.w)));
    #pragma unroll
    for (int o = 16; o > 0; o >>= 1) mx = fmaxf(mx, __shfl_xor_sync(0xffffffff, mx, o));
    if ((t & 31) == 0) sred[t >> 5] = mx;
    __syncthreads();
    if (t < 32) {
        float m2 = (t < 8) ? sred[t] : -1e30f;
        #pragma unroll
        for (int o = 4; o > 0; o >>= 1) m2 = fmaxf(m2, __shfl_xor_sync(0xffffffff, m2, o));
        if (t == 0) sred[0] = m2;
    }
    __syncthreads();
    mx = sred[0];
    __syncthreads();

    v0.x = __expf(v0.x - mx); v0.y = __expf(v0.y - mx);
    v0.z = __expf(v0.z - mx); v0.w = __expf(v0.w - mx);
    v1.x = __expf(v1.x - mx); v1.y = __expf(v1.y - mx);
    v1.z = __expf(v1.z - mx); v1.w = __expf(v1.w - mx);
    float sum = v0.x + v0.y + v0.z + v0.w + v1.x + v1.y + v1.z + v1.w;
    #pragma unroll
    for (int o = 16; o > 0; o >>= 1) sum += __shfl_xor_sync(0xffffffff, sum, o);
    if ((t & 31) == 0) sred[t >> 5] = sum;
    __syncthreads();
    if (t < 32) {
        float s2 = (t < 8) ? sred[t] : 0.f;
        #pragma unroll
        for (int o = 4; o > 0; o >>= 1) s2 += __shfl_xor_sync(0xffffffff, s2, o);
        if (t == 0) sred[0] = s2;
    }
    __syncthreads();
    float inv = 1.0f / sred[0];

    v0.x *= inv; v0.y *= inv; v0.z *= inv; v0.w *= inv;
    v1.x *= inv; v1.y *= inv; v1.z *= inv; v1.w *= inv;
    p[t] = v0;
    p[t + 256] = v1;

    size_t i0 = row * SEQ + 4 * (size_t)t;
    size_t i1 = row * SEQ + 4 * ((size_t)t + 256);
    float a0[4] = {v0.x, v0.y, v0.z, v0.w};
    float a1[4] = {v1.x, v1.y, v1.z, v1.w};
    #pragma unroll
    for (int j = 0; j < 4; j++) {
        __nv_bfloat16 h, l;
        split_bf16(a0[j], h, l); g_whi[i0 + j] = h; g_wlo[i0 + j] = l;
        split_bf16(a1[j], h, l); g_whi[i1 + j] = h; g_wlo[i1 + j] = l;
    }
}

// ---------------------------------------------------------------------------
// AV: per (b,h) O[2048,64] = w @ V.  A = w hi/lo [sq][sk], B = vT [d][sk].
// Block tile 128x64, 8 warps (2m x 4n), warp tile 64x16, BK=32, 64 iters.
// ---------------------------------------------------------------------------
__global__ void __launch_bounds__(256) av_kernel() {
    __shared__ __nv_bfloat16 Ash[128*SA], Asl[128*SA], Bsh[64*SA], Bsl[64*SA];
    int tid = threadIdx.x, lane = tid & 31, warp = tid >> 5;
    int g = lane >> 2, tc = lane & 3;
    int wm = (warp & 1) * 64, wn = (warp >> 1) * 16;
    int m0 = blockIdx.x * 128;
    int bh = blockIdx.y, b = bh >> 4, h = bh & 15;

    const __nv_bfloat16* Ahi = g_whi + ((size_t)bh * SEQ + m0) * SEQ;
    const __nv_bfloat16* Alo = g_wlo + ((size_t)bh * SEQ + m0) * SEQ;
    const __nv_bfloat16* Bhi = g_vThi + (size_t)bh * DEPTH * SEQ;
    const __nv_bfloat16* Blo = g_vTlo + (size_t)bh * DEPTH * SEQ;

    float acc[4][2][4] = {};

    for (int kt = 0; kt < SEQ; kt += 32) {
        #pragma unroll
        for (int i = 0; i < 2; i++) {
            int e = tid + i * 256;
            int r = e >> 2, c8 = (e & 3) * 8;
            size_t ga = (size_t)r * SEQ + kt + c8;
            *(uint4*)&Ash[r*SA + c8] = *(const uint4*)&Ahi[ga];
            *(uint4*)&Asl[r*SA + c8] = *(const uint4*)&Alo[ga];
        }
        {
            int e = tid;
            int r = e >> 2, c8 = (e & 3) * 8;
            size_t gb = (size_t)r * SEQ + kt + c8;
            *(uint4*)&Bsh[r*SA + c8] = *(const uint4*)&Bhi[gb];
            *(uint4*)&Bsl[r*SA + c8] = *(const uint4*)&Blo[gb];
        }
        __syncthreads();
        #pragma unroll
        for (int kk = 0; kk < 32; kk += 16) {
            uint32_t ah[4][4], al[4][4];
            #pragma unroll
            for (int mf = 0; mf < 4; mf++) {
                int r0 = (wm + mf*16 + g) * SA + kk + tc*2;
                int r1 = r0 + 8*SA;
                ah[mf][0] = ld32(&Ash[r0]);   ah[mf][1] = ld32(&Ash[r1]);
                ah[mf][2] = ld32(&Ash[r0+8]); ah[mf][3] = ld32(&Ash[r1+8]);
                al[mf][0] = ld32(&Asl[r0]);   al[mf][1] = ld32(&Asl[r1]);
                al[mf][2] = ld32(&Asl[r0+8]); al[mf][3] = ld32(&Asl[r1+8]);
            }
            #pragma unroll
            for (int nf = 0; nf < 2; nf++) {
                int q0 = (wn + nf*8 + g) * SA + kk + tc*2;
                uint32_t bh0 = ld32(&Bsh[q0]), bh1 = ld32(&Bsh[q0+8]);
                uint32_t bl0 = ld32(&Bsl[q0]), bl1 = ld32(&Bsl[q0+8]);
                #pragma unroll
                for (int mf = 0; mf < 4; mf++) {
                    mma_bf16(acc[mf][nf], ah[mf][0], ah[mf][1], ah[mf][2], ah[mf][3], bh0, bh1);
                    mma_bf16(acc[mf][nf], ah[mf][0], ah[mf][1], ah[mf][2], ah[mf][3], bl0, bl1);
                    mma_bf16(acc[mf][nf], al[mf][0], al[mf][1], al[mf][2], al[mf][3], bh0, bh1);
                }
            }
        }
        __syncthreads();
    }

    #pragma unroll
    for (int mf = 0; mf < 4; mf++) {
        #pragma unroll
        for (int rr = 0; rr < 2; rr++) {
            int s = m0 + wm + mf*16 + g + rr*8;
            size_t base = ((size_t)b * SEQ + s) * DMODEL + h * DEPTH;
            #pragma unroll
            for (int nf = 0; nf < 2; nf++) {
                int d = wn + nf*8 + tc*2;
                float v0 = acc[mf][nf][rr*2+0];
                float v1 = acc[mf][nf][rr*2+1];
                __nv_bfloat16 h0, l0, h1, l1;
                split_bf16(v0, h0, l0); split_bf16(v1, h1, l1);
                __nv_bfloat162 hp; hp.x = h0; hp.y = h1;
                __nv_bfloat162 lp; lp.x = l0; lp.y = l1;
                *(__nv_bfloat162*)&g_athi[base + d] = hp;
                *(__nv_bfloat162*)&g_atlo[base + d] = lp;
            }
        }
    }
}

// ---------------------------------------------------------------------------
// Output projection: out = attn @ Wo + bo (fp32 out)
// ---------------------------------------------------------------------------
__global__ void __launch_bounds__(256) proj_out_kernel(
        const float* __restrict__ bo, float* __restrict__ out) {
    __shared__ __nv_bfloat16 Ash[128*SA], Asl[128*SA], Bsh[128*SA], Bsl[128*SA];
    int tid = threadIdx.x, lane = tid & 31, warp = tid >> 5;
    int g = lane >> 2, tc = lane & 3;
    int wm = (warp & 1) * 64, wn = (warp >> 1) * 32;
    int m0 = blockIdx.y * 128, n0 = blockIdx.x * 128;

    const __nv_bfloat16* Ahi = g_athi;
    const __nv_bfloat16* Alo = g_atlo;
    const __nv_bfloat16* Bhi = g_wThi + 3ULL * DMODEL * DMODEL;
    const __nv_bfloat16* Blo = g_wTlo + 3ULL * DMODEL * DMODEL;

    float acc[4][4][4] = {};

    for (int kt = 0; kt < DMODEL; kt += 32) {
        #pragma unroll
        for (int i = 0; i < 2; i++) {
            int e = tid + i * 256;
            int r = e >> 2, c8 = (e & 3) * 8;
            size_t ga = (size_t)(m0 + r) * DMODEL + kt + c8;
            size_t gb = (size_t)(n0 + r) * DMODEL + kt + c8;
            *(uint4*)&Ash[r*SA + c8] = *(const uint4*)&Ahi[ga];
            *(uint4*)&Asl[r*SA + c8] = *(const uint4*)&Alo[ga];
            *(uint4*)&Bsh[r*SA + c8] = *(const uint4*)&Bhi[gb];
            *(uint4*)&Bsl[r*SA + c8] = *(const uint4*)&Blo[gb];
        }
        __syncthreads();
        #pragma unroll
        for (int kk = 0; kk < 32; kk += 16) {
            uint32_t ah[4][4], al[4][4];
            #pragma unroll
            for (int mf = 0; mf < 4; mf++) {
                int r0 = (wm + mf*16 + g) * SA + kk + tc*2;
                int r1 = r0 + 8*SA;
                ah[mf][0] = ld32(&Ash[r0]);   ah[mf][1] = ld32(&Ash[r1]);
                ah[mf][2] = ld32(&Ash[r0+8]); ah[mf][3] = ld32(&Ash[r1+8]);
                al[mf][0] = ld32(&Asl[r0]);   al[mf][1] = ld32(&Asl[r1]);
                al[mf][2] = ld32(&Asl[r0+8]); al[mf][3] = ld32(&Asl[r1+8]);
            }
            #pragma unroll
            for (int nf = 0; nf < 4; nf++) {
                int q0 = (wn + nf*8 + g) * SA + kk + tc*2;
                uint32_t bh0 = ld32(&Bsh[q0]), bh1 = ld32(&Bsh[q0+8]);
                uint32_t bl0 = ld32(&Bsl[q0]), bl1 = ld32(&Bsl[q0+8]);
                #pragma unroll
                for (int mf = 0; mf < 4; mf++) {
                    mma_bf16(acc[mf][nf], ah[mf][0], ah[mf][1], ah[mf][2], ah[mf][3], bh0, bh1);
                    mma_bf16(acc[mf][nf], ah[mf][0], ah[mf][1], ah[mf][2], ah[mf][3], bl0, bl1);
                    mma_bf16(acc[mf][nf], al[mf][0], al[mf][1], al[mf][2], al[mf][3], bh0, bh1);
                }
            }
        }
        __syncthreads();
    }

    #pragma unroll
    for (int mf = 0; mf < 4; mf++) {
        #pragma unroll
        for (int rr = 0; rr < 2; rr++) {
            int m = m0 + wm + mf*16 + g + rr*8;
            #pragma unroll
            for (int nf = 0; nf < 4; nf++) {
                int n = n0 + wn + nf*8 + tc*2;
                float2 o;
                o.x = acc[mf][nf][rr*2+0] + bo[n];
                o.y = acc[mf][nf][rr*2+1] + bo[n+1];
                *(float2*)&out[(size_t)m * DMODEL + n] = o;
            }
        }
    }
}

// ---------------------------------------------------------------------------
extern "C" void kernel_launch(void* const* d_in, const int* in_sizes, int n_in,
                              void* d_out, int out_size) {
    const float* q    = (const float*)d_in[0];
    const float* k    = (const float*)d_in[1];
    const float* v    = (const float*)d_in[2];
    const float* mask = (const float*)d_in[3];
    const float* Wq   = (const float*)d_in[4];
    const float* bq   = (const float*)d_in[5];
    const float* Wk   = (const float*)d_in[6];
    const float* bk   = (const float*)d_in[7];
    const float* Wv   = (const float*)d_in[8];
    const float* bv   = (const float*)d_in[9];
    const float* Wo   = (const float*)d_in[10];
    const float* bo   = (const float*)d_in[11];

    float* out_main = (float*)d_out;                              // [2,2048,1024]
    float* out_w    = (float*)d_out + (size_t)BS * SEQ * DMODEL;  // [2,16,2048,2048]

    prep_inputs<<<2048, 256>>>(q, k, v);
    prep_weights<<<dim3(32, 32, 4), dim3(32, 8)>>>(Wq, Wk, Wv, Wo);

    proj_qkv_kernel<<<dim3(8, 32, 3), 256>>>(bq, bk, bv);
    transpose_v<<<dim3(32, 1, BH), 256>>>();

    scores_kernel<<<dim3(16, 16, BH), 256>>>(mask, out_w);

    softmax_kernel<<<BH * SEQ, 256>>>(out_w);

    av_kernel<<<dim3(16, BH), 256>>>();

    proj_out_kernel<<<dim3(8, 32), 256>>>(bo, out_main);
}

// round 8
// speedup vs baseline: 2.6821x; 1.4677x over previous
#include <cuda_runtime.h>
#include <cuda_bf16.h>
#include <cstdint>

#define BS 2
#define SEQ 2048
#define DMODEL 1024
#define NHEADS 16
#define DEPTH 64
#define BH (BS*NHEADS)
#define MTOT (BS*SEQ)
#define SA 40    // bf16 smem row stride: (20r) pattern -> conflict-free frag loads
#define SAF 40   // fp32 smem row stride: 8g+2tc distinct per half-warp

// ---------------------------------------------------------------------------
// Device scratch
// ---------------------------------------------------------------------------
__device__ __nv_bfloat16 g_xhi[3ULL*MTOT*DMODEL], g_xlo[3ULL*MTOT*DMODEL];
__device__ __nv_bfloat16 g_wThi[4ULL*DMODEL*DMODEL], g_wTlo[4ULL*DMODEL*DMODEL]; // [z][n][k]
__device__ __nv_bfloat16 g_qhi[(size_t)BH*SEQ*DEPTH], g_qlo[(size_t)BH*SEQ*DEPTH];
__device__ __nv_bfloat16 g_khi[(size_t)BH*SEQ*DEPTH], g_klo[(size_t)BH*SEQ*DEPTH];
__device__ __nv_bfloat16 g_vhi[(size_t)BH*SEQ*DEPTH], g_vlo[(size_t)BH*SEQ*DEPTH];
__device__ __nv_bfloat16 g_vThi[(size_t)BH*DEPTH*SEQ], g_vTlo[(size_t)BH*DEPTH*SEQ];
__device__ __nv_bfloat16 g_athi[(size_t)MTOT*DMODEL], g_atlo[(size_t)MTOT*DMODEL];

// ---------------------------------------------------------------------------
__device__ __forceinline__ void split_bf16(float x, __nv_bfloat16& h, __nv_bfloat16& l) {
    h = __float2bfloat16(x);
    l = __float2bfloat16(x - __bfloat162float(h));
}

__device__ __forceinline__ void split2(float2 f, uint32_t& hi, uint32_t& lo) {
    __nv_bfloat162 h = __float22bfloat162_rn(f);
    float2 r;
    r.x = f.x - __bfloat162float(h.x);
    r.y = f.y - __bfloat162float(h.y);
    __nv_bfloat162 l = __float22bfloat162_rn(r);
    hi = *reinterpret_cast<uint32_t*>(&h);
    lo = *reinterpret_cast<uint32_t*>(&l);
}

__device__ __forceinline__ void mma_bf16(float c[4],
        uint32_t a0, uint32_t a1, uint32_t a2, uint32_t a3,
        uint32_t b0, uint32_t b1) {
    asm volatile(
        "mma.sync.aligned.m16n8k16.row.col.f32.bf16.bf16.f32 "
        "{%0,%1,%2,%3}, {%4,%5,%6,%7}, {%8,%9}, {%0,%1,%2,%3};"
        : "+f"(c[0]), "+f"(c[1]), "+f"(c[2]), "+f"(c[3])
        : "r"(a0), "r"(a1), "r"(a2), "r"(a3), "r"(b0), "r"(b1));
}

__device__ __forceinline__ uint32_t ld32(const __nv_bfloat16* p) {
    return *reinterpret_cast<const uint32_t*>(p);
}

__device__ __forceinline__ uint32_t smem_u32(const void* p) {
    uint32_t a;
    asm("{ .reg .u64 t; cvta.to.shared.u64 t, %1; cvt.u32.u64 %0, t; }" : "=r"(a) : "l"(p));
    return a;
}
__device__ __forceinline__ void cp16(uint32_t dst, const void* src) {
    asm volatile("cp.async.cg.shared.global [%0], [%1], 16;" :: "r"(dst), "l"(src));
}
#define CP_COMMIT() asm volatile("cp.async.commit_group;" ::: "memory")
#define CP_WAIT(n)  asm volatile("cp.async.wait_group %0;" :: "n"(n) : "memory")

// ---------------------------------------------------------------------------
// Prep kernels
// ---------------------------------------------------------------------------
__global__ void prep_inputs(const float* __restrict__ q, const float* __restrict__ k,
                            const float* __restrict__ v) {
    const size_t n1 = (size_t)MTOT * DMODEL;
    const size_t n1v = n1 / 4;
    size_t total = 3 * n1v;
    for (size_t i = blockIdx.x * (size_t)blockDim.x + threadIdx.x; i < total;
         i += (size_t)gridDim.x * blockDim.x) {
        size_t seg = i / n1v;
        size_t off = (i - seg * n1v) * 4;
        const float* src = (seg == 0) ? q : (seg == 1) ? k : v;
        float4 f = *(const float4*)(src + off);
        size_t base = seg * n1 + off;
        __nv_bfloat16 h, l;
        split_bf16(f.x, h, l); g_xhi[base+0] = h; g_xlo[base+0] = l;
        split_bf16(f.y, h, l); g_xhi[base+1] = h; g_xlo[base+1] = l;
        split_bf16(f.z, h, l); g_xhi[base+2] = h; g_xlo[base+2] = l;
        split_bf16(f.w, h, l); g_xhi[base+3] = h; g_xlo[base+3] = l;
    }
}

__global__ void prep_weights(const float* __restrict__ Wq, const float* __restrict__ Wk,
                             const float* __restrict__ Wv, const float* __restrict__ Wo) {
    __shared__ float t[32][33];
    int z = blockIdx.z;
    const float* W = (z == 0) ? Wq : (z == 1) ? Wk : (z == 2) ? Wv : Wo;
    int n0 = blockIdx.x * 32, k0 = blockIdx.y * 32;
    int tx = threadIdx.x, ty = threadIdx.y;
    #pragma unroll
    for (int i = 0; i < 4; i++)
        t[ty + 8*i][tx] = W[(size_t)(k0 + ty + 8*i) * DMODEL + n0 + tx];
    __syncthreads();
    #pragma unroll
    for (int i = 0; i < 4; i++) {
        float x = t[tx][ty + 8*i];
        __nv_bfloat16 h, l; split_bf16(x, h, l);
        size_t idx = ((size_t)z * DMODEL + (n0 + ty + 8*i)) * DMODEL + k0 + tx;
        g_wThi[idx] = h; g_wTlo[idx] = l;
    }
}

// ---------------------------------------------------------------------------
// Shared GEMM machinery (bf16 hi/lo in gmem, cp.async double buffer)
// smem layout per stage (bytes): AHI 0, ALO 10240, BHI 20480, BLO 30720; stage stride 40960
// ---------------------------------------------------------------------------
#define STG_STRIDE 40960
#define OFF_AHI 0
#define OFF_ALO 10240
#define OFF_BHI 20480
#define OFF_BLO 30720
#define SMEM_GEMM (2*STG_STRIDE)

__device__ __forceinline__ void gemm_load_stage(uint32_t sb, int s,
        const __nv_bfloat16* Ahi, const __nv_bfloat16* Alo,
        const __nv_bfloat16* Bhi, const __nv_bfloat16* Blo,
        int lda, int ldb, int kt, int tid) {
    uint32_t base = sb + s * STG_STRIDE;
    #pragma unroll
    for (int i = 0; i < 2; i++) {
        int e = tid + i * 256;
        int r = e >> 2, c8 = (e & 3) * 8;
        uint32_t so = r * (SA*2) + c8 * 2;
        size_t ga = (size_t)r * lda + kt + c8;
        size_t gb = (size_t)r * ldb + kt + c8;
        cp16(base + OFF_AHI + so, Ahi + ga);
        cp16(base + OFF_ALO + so, Alo + ga);
        cp16(base + OFF_BHI + so, Bhi + gb);
        cp16(base + OFF_BLO + so, Blo + gb);
    }
}

// compute one 128x128 stage, 3-term split; acc[4][4][4]
__device__ __forceinline__ void gemm_compute_stage(char* smem, int s,
        int wm, int wn, int g, int tc, float acc[4][4][4]) {
    const __nv_bfloat16* Ash = (const __nv_bfloat16*)(smem + s*STG_STRIDE + OFF_AHI);
    const __nv_bfloat16* Asl = (const __nv_bfloat16*)(smem + s*STG_STRIDE + OFF_ALO);
    const __nv_bfloat16* Bsh = (const __nv_bfloat16*)(smem + s*STG_STRIDE + OFF_BHI);
    const __nv_bfloat16* Bsl = (const __nv_bfloat16*)(smem + s*STG_STRIDE + OFF_BLO);
    #pragma unroll
    for (int kk = 0; kk < 32; kk += 16) {
        uint32_t ah[4][4], al[4][4];
        #pragma unroll
        for (int mf = 0; mf < 4; mf++) {
            int r0 = (wm + mf*16 + g) * SA + kk + tc*2;
            int r1 = r0 + 8*SA;
            ah[mf][0] = ld32(&Ash[r0]);   ah[mf][1] = ld32(&Ash[r1]);
            ah[mf][2] = ld32(&Ash[r0+8]); ah[mf][3] = ld32(&Ash[r1+8]);
            al[mf][0] = ld32(&Asl[r0]);   al[mf][1] = ld32(&Asl[r1]);
            al[mf][2] = ld32(&Asl[r0+8]); al[mf][3] = ld32(&Asl[r1+8]);
        }
        #pragma unroll
        for (int nf = 0; nf < 4; nf++) {
            int q0 = (wn + nf*8 + g) * SA + kk + tc*2;
            uint32_t bh0 = ld32(&Bsh[q0]), bh1 = ld32(&Bsh[q0+8]);
            uint32_t bl0 = ld32(&Bsl[q0]), bl1 = ld32(&Bsl[q0+8]);
            #pragma unroll
            for (int mf = 0; mf < 4; mf++) {
                mma_bf16(acc[mf][nf], ah[mf][0], ah[mf][1], ah[mf][2], ah[mf][3], bh0, bh1);
                mma_bf16(acc[mf][nf], ah[mf][0], ah[mf][1], ah[mf][2], ah[mf][3], bl0, bl1);
                mma_bf16(acc[mf][nf], al[mf][0], al[mf][1], al[mf][2], al[mf][3], bh0, bh1);
            }
        }
    }
}

// ---------------------------------------------------------------------------
// QKV projection
// ---------------------------------------------------------------------------
__global__ void __launch_bounds__(256) proj_qkv_kernel(
        const float* __restrict__ bq, const float* __restrict__ bk,
        const float* __restrict__ bv) {
    extern __shared__ char smem[];
    uint32_t sb = smem_u32(smem);
    int tid = threadIdx.x, lane = tid & 31, warp = tid >> 5;
    int g = lane >> 2, tc = lane & 3;
    int wm = (warp & 1) * 64, wn = (warp >> 1) * 32;
    int z = blockIdx.z;
    int m0 = blockIdx.y * 128, n0 = blockIdx.x * 128;

    const __nv_bfloat16* Ahi = g_xhi + (size_t)z * MTOT * DMODEL + (size_t)m0 * DMODEL;
    const __nv_bfloat16* Alo = g_xlo + (size_t)z * MTOT * DMODEL + (size_t)m0 * DMODEL;
    const __nv_bfloat16* Bhi = g_wThi + (size_t)z * DMODEL * DMODEL + (size_t)n0 * DMODEL;
    const __nv_bfloat16* Blo = g_wTlo + (size_t)z * DMODEL * DMODEL + (size_t)n0 * DMODEL;
    const float* bias = (z == 0) ? bq : (z == 1) ? bk : bv;

    float acc[4][4][4] = {};
    const int NT = DMODEL / 32;

    gemm_load_stage(sb, 0, Ahi, Alo, Bhi, Blo, DMODEL, DMODEL, 0, tid);
    CP_COMMIT();
    for (int i = 0; i < NT; i++) {
        if (i + 1 < NT) {
            gemm_load_stage(sb, (i+1)&1, Ahi, Alo, Bhi, Blo, DMODEL, DMODEL, (i+1)*32, tid);
            CP_COMMIT();
            CP_WAIT(1);
        } else {
            CP_WAIT(0);
        }
        __syncthreads();
        gemm_compute_stage(smem, i&1, wm, wn, g, tc, acc);
        __syncthreads();
    }

    __nv_bfloat16 *Dh, *Dl;
    if (z == 0) { Dh = g_qhi; Dl = g_qlo; }
    else if (z == 1) { Dh = g_khi; Dl = g_klo; }
    else { Dh = g_vhi; Dl = g_vlo; }

    #pragma unroll
    for (int mf = 0; mf < 4; mf++) {
        #pragma unroll
        for (int rr = 0; rr < 2; rr++) {
            int m = m0 + wm + mf*16 + g + rr*8;
            int b = m >> 11, s = m & (SEQ-1);
            #pragma unroll
            for (int nf = 0; nf < 4; nf++) {
                int n = n0 + wn + nf*8 + tc*2;
                int h = n >> 6, d = n & 63;
                float v0 = acc[mf][nf][rr*2+0] + bias[n];
                float v1 = acc[mf][nf][rr*2+1] + bias[n+1];
                __nv_bfloat16 h0, l0, h1, l1;
                split_bf16(v0, h0, l0); split_bf16(v1, h1, l1);
                size_t base = ((size_t)(b*NHEADS + h) * SEQ + s) * DEPTH + d;
                __nv_bfloat162 hp; hp.x = h0; hp.y = h1;
                __nv_bfloat162 lp; lp.x = l0; lp.y = l1;
                *(__nv_bfloat162*)&Dh[base] = hp;
                *(__nv_bfloat162*)&Dl[base] = lp;
            }
        }
    }
}

// ---------------------------------------------------------------------------
// Transpose V -> vT
// ---------------------------------------------------------------------------
__global__ void __launch_bounds__(256) transpose_v() {
    __shared__ __nv_bfloat16 th[64][66], tl[64][66];
    int bh = blockIdx.z, s0 = blockIdx.x * 64;
    int tid = threadIdx.x;
    #pragma unroll
    for (int i = 0; i < 8; i++) {
        int e = tid + i * 256;
        int r = e >> 5, c2 = (e & 31) * 2;
        size_t gsrc = ((size_t)bh * SEQ + s0 + r) * DEPTH + c2;
        *(uint32_t*)&th[r][c2] = *(const uint32_t*)&g_vhi[gsrc];
        *(uint32_t*)&tl[r][c2] = *(const uint32_t*)&g_vlo[gsrc];
    }
    __syncthreads();
    #pragma unroll
    for (int i = 0; i < 8; i++) {
        int e = tid + i * 256;
        int d = e >> 5, s2 = (e & 31) * 2;
        size_t gdst = ((size_t)bh * DEPTH + d) * SEQ + s0 + s2;
        __nv_bfloat162 ph; ph.x = th[s2][d]; ph.y = th[s2+1][d];
        __nv_bfloat162 pl; pl.x = tl[s2][d]; pl.y = tl[s2+1][d];
        *(__nv_bfloat162*)&g_vThi[gdst] = ph;
        *(__nv_bfloat162*)&g_vTlo[gdst] = pl;
    }
}

// ---------------------------------------------------------------------------
// Scores
// ---------------------------------------------------------------------------
__global__ void __launch_bounds__(256) scores_kernel(
        const float* __restrict__ mask, float* __restrict__ w) {
    extern __shared__ char smem[];
    uint32_t sb = smem_u32(smem);
    int tid = threadIdx.x, lane = tid & 31, warp = tid >> 5;
    int g = lane >> 2, tc = lane & 3;
    int wm = (warp & 1) * 64, wn = (warp >> 1) * 32;
    int m0 = blockIdx.y * 128, n0 = blockIdx.x * 128;
    int bh = blockIdx.z, b = bh >> 4;

    const __nv_bfloat16* Ahi = g_qhi + ((size_t)bh * SEQ + m0) * DEPTH;
    const __nv_bfloat16* Alo = g_qlo + ((size_t)bh * SEQ + m0) * DEPTH;
    const __nv_bfloat16* Bhi = g_khi + ((size_t)bh * SEQ + n0) * DEPTH;
    const __nv_bfloat16* Blo = g_klo + ((size_t)bh * SEQ + n0) * DEPTH;

    float acc[4][4][4] = {};
    const int NT = DEPTH / 32;

    gemm_load_stage(sb, 0, Ahi, Alo, Bhi, Blo, DEPTH, DEPTH, 0, tid);
    CP_COMMIT();
    for (int i = 0; i < NT; i++) {
        if (i + 1 < NT) {
            gemm_load_stage(sb, (i+1)&1, Ahi, Alo, Bhi, Blo, DEPTH, DEPTH, (i+1)*32, tid);
            CP_COMMIT();
            CP_WAIT(1);
        } else {
            CP_WAIT(0);
        }
        __syncthreads();
        gemm_compute_stage(smem, i&1, wm, wn, g, tc, acc);
        __syncthreads();
    }

    #pragma unroll
    for (int mf = 0; mf < 4; mf++) {
        #pragma unroll
        for (int rr = 0; rr < 2; rr++) {
            int m = m0 + wm + mf*16 + g + rr*8;
            size_t rowb = ((size_t)bh * SEQ + m) * SEQ;
            #pragma unroll
            for (int nf = 0; nf < 4; nf++) {
                int n = n0 + wn + nf*8 + tc*2;
                float2 o;
                o.x = acc[mf][nf][rr*2+0] * 0.125f + mask[(size_t)b*SEQ + n] * (-1e9f);
                o.y = acc[mf][nf][rr*2+1] * 0.125f + mask[(size_t)b*SEQ + n + 1] * (-1e9f);
                *(float2*)&w[rowb + n] = o;
            }
        }
    }
}

// ---------------------------------------------------------------------------
// Softmax in place (fp32 only)
// ---------------------------------------------------------------------------
__global__ void __launch_bounds__(256) softmax_kernel(float* __restrict__ w) {
    __shared__ float sred[32];
    size_t row = blockIdx.x;
    float4* p = (float4*)(w + row * SEQ);
    int t = threadIdx.x;

    float4 v0 = p[t];
    float4 v1 = p[t + 256];
    float mx = fmaxf(fmaxf(fmaxf(v0.x, v0.y), fmaxf(v0.z, v0.w)),
                     fmaxf(fmaxf(v1.x, v1.y), fmaxf(v1.z, v1.w)));
    #pragma unroll
    for (int o = 16; o > 0; o >>= 1) mx = fmaxf(mx, __shfl_xor_sync(0xffffffff, mx, o));
    if ((t & 31) == 0) sred[t >> 5] = mx;
    __syncthreads();
    if (t < 32) {
        float m2 = (t < 8) ? sred[t] : -1e30f;
        #pragma unroll
        for (int o = 4; o > 0; o >>= 1) m2 = fmaxf(m2, __shfl_xor_sync(0xffffffff, m2, o));
        if (t == 0) sred[0] = m2;
    }
    __syncthreads();
    mx = sred[0];
    __syncthreads();

    v0.x = __expf(v0.x - mx); v0.y = __expf(v0.y - mx);
    v0.z = __expf(v0.z - mx); v0.w = __expf(v0.w - mx);
    v1.x = __expf(v1.x - mx); v1.y = __expf(v1.y - mx);
    v1.z = __expf(v1.z - mx); v1.w = __expf(v1.w - mx);
    float sum = v0.x + v0.y + v0.z + v0.w + v1.x + v1.y + v1.z + v1.w;
    #pragma unroll
    for (int o = 16; o > 0; o >>= 1) sum += __shfl_xor_sync(0xffffffff, sum, o);
    if ((t & 31) == 0) sred[t >> 5] = sum;
    __syncthreads();
    if (t < 32) {
        float s2 = (t < 8) ? sred[t] : 0.f;
        #pragma unroll
        for (int o = 4; o > 0; o >>= 1) s2 += __shfl_xor_sync(0xffffffff, s2, o);
        if (t == 0) sred[0] = s2;
    }
    __syncthreads();
    float inv = 1.0f / sred[0];

    v0.x *= inv; v0.y *= inv; v0.z *= inv; v0.w *= inv;
    v1.x *= inv; v1.y *= inv; v1.z *= inv; v1.w *= inv;
    p[t] = v0;
    p[t + 256] = v1;
}

// ---------------------------------------------------------------------------
// AV: reads fp32 w directly; in-register bf16 hi/lo split for A fragments.
// smem: Afp32 stage s at s*20480 (128 x SAF fp32);
//       B bf16 at 40960 + s*10240: BHI +0, BLO +5120 (64 x SA)
// ---------------------------------------------------------------------------
#define AV_AFP(s)  ((s)*20480)
#define AV_BHI(s)  (40960 + (s)*10240)
#define AV_BLO(s)  (40960 + (s)*10240 + 5120)
#define SMEM_AV    61440

__device__ __forceinline__ void av_load_stage(uint32_t sb, int s,
        const float* Aw, const __nv_bfloat16* Bhi, const __nv_bfloat16* Blo,
        int kt, int tid) {
    // A: 128 x 32 fp32 -> 1024 chunks of 16B; 4 per thread
    #pragma unroll
    for (int i = 0; i < 4; i++) {
        int e = tid + i * 256;
        int r = e >> 3, c4 = (e & 7) * 4;           // 4 floats per chunk
        cp16(sb + AV_AFP(s) + (r * SAF + c4) * 4, Aw + (size_t)r * SEQ + kt + c4);
    }
    // B: 64 x 32 bf16 hi/lo -> 256 chunks each; 1 per thread
    {
        int r = tid >> 2, c8 = (tid & 3) * 8;
        uint32_t so = (r * SA + c8) * 2;
        size_t gb = (size_t)r * SEQ + kt + c8;
        cp16(sb + AV_BHI(s) + so, Bhi + gb);
        cp16(sb + AV_BLO(s) + so, Blo + gb);
    }
}

__global__ void __launch_bounds__(256) av_kernel(const float* __restrict__ w) {
    extern __shared__ char smem[];
    uint32_t sb = smem_u32(smem);
    int tid = threadIdx.x, lane = tid & 31, warp = tid >> 5;
    int g = lane >> 2, tc = lane & 3;
    int wm = (warp & 1) * 64, wn = (warp >> 1) * 16;
    int m0 = blockIdx.x * 128;
    int bh = blockIdx.y, b = bh >> 4, h = bh & 15;

    const float* Aw = w + ((size_t)bh * SEQ + m0) * SEQ;
    const __nv_bfloat16* Bhi = g_vThi + (size_t)bh * DEPTH * SEQ;
    const __nv_bfloat16* Blo = g_vTlo + (size_t)bh * DEPTH * SEQ;

    float acc[4][2][4] = {};
    const int NT = SEQ / 32;

    av_load_stage(sb, 0, Aw, Bhi, Blo, 0, tid);
    CP_COMMIT();
    for (int i = 0; i < NT; i++) {
        if (i + 1 < NT) {
            av_load_stage(sb, (i+1)&1, Aw, Bhi, Blo, (i+1)*32, tid);
            CP_COMMIT();
            CP_WAIT(1);
        } else {
            CP_WAIT(0);
        }
        __syncthreads();

        int s = i & 1;
        const float* Af = (const float*)(smem + AV_AFP(s));
        const __nv_bfloat16* Bh = (const __nv_bfloat16*)(smem + AV_BHI(s));
        const __nv_bfloat16* Bl = (const __nv_bfloat16*)(smem + AV_BLO(s));

        #pragma unroll
        for (int kk = 0; kk < 32; kk += 16) {
            uint32_t ah[4][4], al[4][4];
            #pragma unroll
            for (int mf = 0; mf < 4; mf++) {
                int r0 = (wm + mf*16 + g) * SAF + kk + tc*2;
                int r1 = r0 + 8*SAF;
                split2(*(const float2*)&Af[r0],   ah[mf][0], al[mf][0]);
                split2(*(const float2*)&Af[r1],   ah[mf][1], al[mf][1]);
                split2(*(const float2*)&Af[r0+8], ah[mf][2], al[mf][2]);
                split2(*(const float2*)&Af[r1+8], ah[mf][3], al[mf][3]);
            }
            #pragma unroll
            for (int nf = 0; nf < 2; nf++) {
                int q0 = (wn + nf*8 + g) * SA + kk + tc*2;
                uint32_t bh0 = ld32(&Bh[q0]), bh1 = ld32(&Bh[q0+8]);
                uint32_t bl0 = ld32(&Bl[q0]), bl1 = ld32(&Bl[q0+8]);
                #pragma unroll
                for (int mf = 0; mf < 4; mf++) {
                    mma_bf16(acc[mf][nf], ah[mf][0], ah[mf][1], ah[mf][2], ah[mf][3], bh0, bh1);
                    mma_bf16(acc[mf][nf], ah[mf][0], ah[mf][1], ah[mf][2], ah[mf][3], bl0, bl1);
                    mma_bf16(acc[mf][nf], al[mf][0], al[mf][1], al[mf][2], al[mf][3], bh0, bh1);
                }
            }
        }
        __syncthreads();
    }

    #pragma unroll
    for (int mf = 0; mf < 4; mf++) {
        #pragma unroll
        for (int rr = 0; rr < 2; rr++) {
            int s = m0 + wm + mf*16 + g + rr*8;
            size_t base = ((size_t)b * SEQ + s) * DMODEL + h * DEPTH;
            #pragma unroll
            for (int nf = 0; nf < 2; nf++) {
                int d = wn + nf*8 + tc*2;
                float v0 = acc[mf][nf][rr*2+0];
                float v1 = acc[mf][nf][rr*2+1];
                __nv_bfloat16 h0, l0, h1, l1;
                split_bf16(v0, h0, l0); split_bf16(v1, h1, l1);
                __nv_bfloat162 hp; hp.x = h0; hp.y = h1;
                __nv_bfloat162 lp; lp.x = l0; lp.y = l1;
                *(__nv_bfloat162*)&g_athi[base + d] = hp;
                *(__nv_bfloat162*)&g_atlo[base + d] = lp;
            }
        }
    }
}

// ---------------------------------------------------------------------------
// Output projection
// ---------------------------------------------------------------------------
__global__ void __launch_bounds__(256) proj_out_kernel(
        const float* __restrict__ bo, float* __restrict__ out) {
    extern __shared__ char smem[];
    uint32_t sb = smem_u32(smem);
    int tid = threadIdx.x, lane = tid & 31, warp = tid >> 5;
    int g = lane >> 2, tc = lane & 3;
    int wm = (warp & 1) * 64, wn = (warp >> 1) * 32;
    int m0 = blockIdx.y * 128, n0 = blockIdx.x * 128;

    const __nv_bfloat16* Ahi = g_athi + (size_t)m0 * DMODEL;
    const __nv_bfloat16* Alo = g_atlo + (size_t)m0 * DMODEL;
    const __nv_bfloat16* Bhi = g_wThi + 3ULL * DMODEL * DMODEL + (size_t)n0 * DMODEL;
    const __nv_bfloat16* Blo = g_wTlo + 3ULL * DMODEL * DMODEL + (size_t)n0 * DMODEL;

    float acc[4][4][4] = {};
    const int NT = DMODEL / 32;

    gemm_load_stage(sb, 0, Ahi, Alo, Bhi, Blo, DMODEL, DMODEL, 0, tid);
    CP_COMMIT();
    for (int i = 0; i < NT; i++) {
        if (i + 1 < NT) {
            gemm_load_stage(sb, (i+1)&1, Ahi, Alo, Bhi, Blo, DMODEL, DMODEL, (i+1)*32, tid);
            CP_COMMIT();
            CP_WAIT(1);
        } else {
            CP_WAIT(0);
        }
        __syncthreads();
        gemm_compute_stage(smem, i&1, wm, wn, g, tc, acc);
        __syncthreads();
    }

    #pragma unroll
    for (int mf = 0; mf < 4; mf++) {
        #pragma unroll
        for (int rr = 0; rr < 2; rr++) {
            int m = m0 + wm + mf*16 + g + rr*8;
            #pragma unroll
            for (int nf = 0; nf < 4; nf++) {
                int n = n0 + wn + nf*8 + tc*2;
                float2 o;
                o.x = acc[mf][nf][rr*2+0] + bo[n];
                o.y = acc[mf][nf][rr*2+1] + bo[n+1];
                *(float2*)&out[(size_t)m * DMODEL + n] = o;
            }
        }
    }
}

// ---------------------------------------------------------------------------
extern "C" void kernel_launch(void* const* d_in, const int* in_sizes, int n_in,
                              void* d_out, int out_size) {
    const float* q    = (const float*)d_in[0];
    const float* k    = (const float*)d_in[1];
    const float* v    = (const float*)d_in[2];
    const float* mask = (const float*)d_in[3];
    const float* Wq   = (const float*)d_in[4];
    const float* bq   = (const float*)d_in[5];
    const float* Wk   = (const float*)d_in[6];
    const float* bk   = (const float*)d_in[7];
    const float* Wv   = (const float*)d_in[8];
    const float* bv   = (const float*)d_in[9];
    const float* Wo   = (const float*)d_in[10];
    const float* bo   = (const float*)d_in[11];

    float* out_main = (float*)d_out;                              // [2,2048,1024]
    float* out_w    = (float*)d_out + (size_t)BS * SEQ * DMODEL;  // [2,16,2048,2048]

    static bool attr_done = false;
    if (!attr_done) {
        cudaFuncSetAttribute(proj_qkv_kernel, cudaFuncAttributeMaxDynamicSharedMemorySize, SMEM_GEMM);
        cudaFuncSetAttribute(scores_kernel,   cudaFuncAttributeMaxDynamicSharedMemorySize, SMEM_GEMM);
        cudaFuncSetAttribute(av_kernel,       cudaFuncAttributeMaxDynamicSharedMemorySize, SMEM_AV);
        cudaFuncSetAttribute(proj_out_kernel, cudaFuncAttributeMaxDynamicSharedMemorySize, SMEM_GEMM);
        attr_done = true;
    }

    prep_inputs<<<2048, 256>>>(q, k, v);
    prep_weights<<<dim3(32, 32, 4), dim3(32, 8)>>>(Wq, Wk, Wv, Wo);

    proj_qkv_kernel<<<dim3(8, 32, 3), 256, SMEM_GEMM>>>(bq, bk, bv);
    transpose_v<<<dim3(32, 1, BH), 256>>>();

    scores_kernel<<<dim3(16, 16, BH), 256, SMEM_GEMM>>>(mask, out_w);

    softmax_kernel<<<BH * SEQ, 256>>>(out_w);

    av_kernel<<<dim3(16, BH), 256, SMEM_AV>>>(out_w);

    proj_out_kernel<<<dim3(8, 32), 256, SMEM_GEMM>>>(bo, out_main);
}